// round 12
// baseline (speedup 1.0000x reference)
#include <cuda_runtime.h>
#include <cuda_bf16.h>
#include <cfloat>
#include <cstdint>

#define NUM_HEADS 4
#define OUT_DIM   256
#define HID       512
#define NQ        256
#define TOPK      16
#define N_MEM_MAX 500000
#define CAND      32
#define CPL       4                       // top-4 per (lane, q) slice
#define NBLK_MAX  152
#define POOL_MAX  (NBLK_MAX * 32)         // 4864 per query (32 per block)
#define PMAX_PAD  4864                    // 19 * 256

// ---------------- static scratch ---------------------------------------------
__device__ __align__(16) float          g_qpre[64 * NUM_HEADS * OUT_DIM];
__device__ __align__(16) float          g_q [NQ * OUT_DIM];
__device__ __align__(16) __nv_bfloat16  g_qb[NQ * OUT_DIM];
__device__ float g_cand_val[NQ * POOL_MAX];
__device__ int   g_cand_idx[NQ * POOL_MAX];

// ---------------- helpers ------------------------------------------------------
__device__ __forceinline__ uint32_t smem_u32(const void* p) {
    return (uint32_t)__cvta_generic_to_shared(p);
}
// pack high halves of two fp32 -> bf16x2 (truncation; pure ALU, the only cheap cvt)
__device__ __forceinline__ uint32_t bf16x2_trunc(float lo, float hi) {
    uint32_t r;
    asm("prmt.b32 %0, %1, %2, 0x7632;" : "=r"(r) : "r"(__float_as_uint(lo)), "r"(__float_as_uint(hi)));
    return r;
}
__device__ __forceinline__ void ldsm_x4(uint32_t& r0, uint32_t& r1, uint32_t& r2, uint32_t& r3,
                                        uint32_t addr) {
    asm volatile("ldmatrix.sync.aligned.m8n8.x4.shared.b16 {%0,%1,%2,%3}, [%4];"
                 : "=r"(r0), "=r"(r1), "=r"(r2), "=r"(r3) : "r"(addr));
}
__device__ __forceinline__ void mma_bf16(float* d,
                                         uint32_t a0, uint32_t a1, uint32_t a2, uint32_t a3,
                                         uint32_t b0, uint32_t b1) {
    asm volatile("mma.sync.aligned.m16n8k16.row.col.f32.bf16.bf16.f32 "
                 "{%0,%1,%2,%3}, {%4,%5,%6,%7}, {%8,%9}, {%0,%1,%2,%3};"
                 : "+f"(d[0]), "+f"(d[1]), "+f"(d[2]), "+f"(d[3])
                 : "r"(a0), "r"(a1), "r"(a2), "r"(a3), "r"(b0), "r"(b1));
}
__device__ __forceinline__ unsigned long long sort_key(float v, int idx) {
    uint32_t fb = __float_as_uint(v);
    fb ^= (fb & 0x80000000u) ? 0xFFFFFFFFu : 0x80000000u;
    return ((unsigned long long)fb << 32) | (uint32_t)(~idx);
}

// ---------------- K1a: proj = hidden @ Wp + bp (128 blocks) -------------------
__global__ __launch_bounds__(256) void proj_kernel(const float* __restrict__ hidden,
                                                   const float* __restrict__ Wp,
                                                   const float* __restrict__ bp) {
    const int tid = threadIdx.x;
    const int jb = blockIdx.x & 31, bh = blockIdx.x >> 5;
    const int j  = jb * 32 + (tid & 31);
    const int b0 = bh * 16 + (tid >> 5) * 2;
    float acc0 = 0.f, acc1 = 0.f;
#pragma unroll 4
    for (int k = 0; k < HID; k++) {
        const float wv = __ldg(&Wp[k * (NUM_HEADS * OUT_DIM) + j]);
        acc0 = fmaf(__ldg(&hidden[(b0 + 0) * HID + k]), wv, acc0);
        acc1 = fmaf(__ldg(&hidden[(b0 + 1) * HID + k]), wv, acc1);
    }
    const float bias = __ldg(&bp[j]);
    g_qpre[(b0 + 0) * (NUM_HEADS * OUT_DIM) + j] = acc0 + bias;
    g_qpre[(b0 + 1) * (NUM_HEADS * OUT_DIM) + j] = acc1 + bias;
}

// ---------------- K1b: layernorm ----------------------------------------------
__global__ __launch_bounds__(256) void ln_kernel() {
    __shared__ float red[OUT_DIM];
    const int qidx = blockIdx.x;
    const int h = qidx >> 6, b = qidx & 63, d = threadIdx.x;

    const float x = g_qpre[b * (NUM_HEADS * OUT_DIM) + h * OUT_DIM + d];
    red[d] = x; __syncthreads();
    for (int s = 128; s > 0; s >>= 1) { if (d < s) red[d] += red[d + s]; __syncthreads(); }
    const float mean = red[0] * (1.0f / OUT_DIM);
    __syncthreads();
    const float dx = x - mean;
    red[d] = dx * dx; __syncthreads();
    for (int s = 128; s > 0; s >>= 1) { if (d < s) red[d] += red[d + s]; __syncthreads(); }
    const float var = red[0] * (1.0f / OUT_DIM);

    const float o = dx * rsqrtf(var + 1e-5f);
    g_q [qidx * OUT_DIM + d] = o;
    g_qb[qidx * OUT_DIM + d] = __float2bfloat16(o);
}

// ---------------- K2: bf16 mma, register-resident selection, no score buffer --
#define K2_THREADS 512
#define TROWS 32
#define LDB   264
#define LDBB  (LDB * 2)                  // 528
#define B_BYTES (NQ * LDBB)              // 135168
#define A_BYTES (TROWS * LDBB)           // 16896
#define A_OFF   B_BYTES
#define K2_SMEM (A_OFF + 3 * A_BYTES)    // 185856

// insert (v, r) into per-q4 top-4 list
#define INS(q4, v, r)                                                     \
    do {                                                                  \
        sv[q4][smin[q4]] = (v); si_[q4][smin[q4]] = (r);                  \
        float m_ = sv[q4][0]; int p_ = 0;                                 \
        _Pragma("unroll")                                                 \
        for (int jj = 1; jj < CPL; jj++)                                  \
            if (sv[q4][jj] < m_) { m_ = sv[q4][jj]; p_ = jj; }            \
        tmin[q4] = m_; smin[q4] = p_;                                     \
    } while (0)

__global__ __launch_bounds__(K2_THREADS, 1) void score_kernel(const float* __restrict__ mem,
                                                              int n_mem, int ntiles) {
    extern __shared__ char sm[];
    char* Bs = sm;                        // queries bf16 [256][LDB]
    const uint32_t sb = smem_u32(sm);

    const int tid = threadIdx.x, lane = tid & 31, w = tid >> 5;   // 16 warps
    const int rowoff = lane >> 2;

    // B fill: 256 queries x 512B bf16
    {
        const uint2* src = (const uint2*)g_qb;
        for (int p = tid; p < NQ * 64; p += K2_THREADS) {
            const int q = p >> 6, c4 = p & 63;
            *(uint2*)(Bs + q * LDBB + c4 * 8) = src[p];
        }
    }

    // per-(lane, q-slot) top-4 (4 q-slots per lane)
    float sv[4][CPL]; int si_[4][CPL];
    float tmin[4]; int smin[4];
#pragma unroll
    for (int qq = 0; qq < 4; qq++) {
#pragma unroll
        for (int j = 0; j < CPL; j++) { sv[qq][j] = -FLT_MAX; si_[qq][j] = 0x7FFFFFFF; }
        tmin[qq] = -FLT_MAX; smin[qq] = 0;
    }

    // A loader: thread -> row tid>>4 (0..31), float col (tid&15)*16
    const int ar = tid >> 4, ac = (tid & 15) * 16;
    const uint32_t asts0 = sb + A_OFF + ar * LDBB + ac * 2;

    float4 f[4];
#define LDG_T(tl)                                                                   \
    do {                                                                            \
        const int rg_ = (tl) * TROWS + ar;                                          \
        if (rg_ < n_mem) {                                                          \
            const float4* s = (const float4*)(mem + (size_t)rg_ * OUT_DIM + ac);    \
            f[0] = s[0]; f[1] = s[1]; f[2] = s[2]; f[3] = s[3];                     \
        } else {                                                                    \
            f[0] = f[1] = f[2] = f[3] = make_float4(0.f, 0.f, 0.f, 0.f);            \
        }                                                                           \
    } while (0)

#define STS_T(bufi)                                                                 \
    do {                                                                            \
        const uint32_t d = asts0 + (bufi) * A_BYTES;                                \
        uint4 o0, o1;                                                               \
        o0.x = bf16x2_trunc(f[0].x, f[0].y); o0.y = bf16x2_trunc(f[0].z, f[0].w);   \
        o0.z = bf16x2_trunc(f[1].x, f[1].y); o0.w = bf16x2_trunc(f[1].z, f[1].w);   \
        o1.x = bf16x2_trunc(f[2].x, f[2].y); o1.y = bf16x2_trunc(f[2].z, f[2].w);   \
        o1.z = bf16x2_trunc(f[3].x, f[3].y); o1.w = bf16x2_trunc(f[3].z, f[3].w);   \
        asm volatile("st.shared.v4.b32 [%0], {%1,%2,%3,%4};" ::                     \
            "r"(d), "r"(o0.x), "r"(o0.y), "r"(o0.z), "r"(o0.w) : "memory");         \
        asm volatile("st.shared.v4.b32 [%0], {%1,%2,%3,%4};" ::                     \
            "r"(d + 16), "r"(o1.x), "r"(o1.y), "r"(o1.z), "r"(o1.w) : "memory");    \
    } while (0)

    // prologue: stage tile t0 into buf0, prefetch t1 into regs
    LDG_T(blockIdx.x);
    STS_T(0);
    {
        const int t1 = blockIdx.x + gridDim.x;
        if (t1 < ntiles) LDG_T(t1);
    }
    __syncthreads();

    // warp tile: 32 rows x 16 queries (q block = w*16)
    const uint32_t bB = sb + (w * 16 + (lane & 15)) * LDBB + (lane >> 4) * 16;

    int it = 0, cur = 0, nxt = 1;
    for (int t = blockIdx.x; t < ntiles; t += gridDim.x, it++) {
        const int tn  = t + gridDim.x;
        const int tn2 = t + 2 * gridDim.x;

        if (tn < ntiles) STS_T(nxt);      // stage t+1 (buf free since mma(t-2))
        if (tn2 < ntiles) LDG_T(tn2);     // prefetch t+2 into regs

        const uint32_t aB = sb + A_OFF + cur * A_BYTES
                          + (lane & 15) * LDBB + (lane >> 4) * 16;

        float acc[2][2][4];
#pragma unroll
        for (int mt = 0; mt < 2; mt++)
#pragma unroll
            for (int nt = 0; nt < 2; nt++)
#pragma unroll
                for (int c = 0; c < 4; c++) acc[mt][nt][c] = 0.f;

#pragma unroll
        for (int kt = 0; kt < 16; kt++) {
            uint32_t a0, a1, a2, a3, a4, a5, a6, a7;
            ldsm_x4(a0, a1, a2, a3, aB + kt * 32);
            ldsm_x4(a4, a5, a6, a7, aB + 16 * LDBB + kt * 32);
            uint32_t b0, b1, b2, b3;
            ldsm_x4(b0, b1, b2, b3, bB + kt * 32);
            mma_bf16(acc[0][0], a0, a1, a2, a3, b0, b2);
            mma_bf16(acc[0][1], a0, a1, a2, a3, b1, b3);
            mma_bf16(acc[1][0], a4, a5, a6, a7, b0, b2);
            mma_bf16(acc[1][1], a4, a5, a6, a7, b1, b3);
        }

        // register-resident selection: lane owns (rows, q) per mma fragment map
        {
            const int rb = t * TROWS + rowoff;
#pragma unroll
            for (int mt = 0; mt < 2; mt++)
#pragma unroll
                for (int nt = 0; nt < 2; nt++)
#pragma unroll
                    for (int c = 0; c < 4; c++) {
                        const float v = acc[mt][nt][c];
                        const int q4 = nt * 2 + (c & 1);
                        if (v > tmin[q4]) {
                            const int row = rb + mt * 16 + ((c >> 1) << 3);
                            if (row < n_mem) INS(q4, v, row);
                        }
                    }
        }

        __syncthreads();   // A[nxt] visible; A[cur] reads done
        cur = nxt; nxt = (nxt == 2) ? 0 : nxt + 1;
    }

    // write pool: 32 candidates per (query, block) = 8 row-slices x 4
#pragma unroll
    for (int nt = 0; nt < 2; nt++)
#pragma unroll
        for (int cb = 0; cb < 2; cb++) {
            const int q4 = nt * 2 + cb;
            const int q = w * 16 + nt * 8 + (lane & 3) * 2 + cb;
            const size_t ob = ((size_t)q * gridDim.x + blockIdx.x) * 32 + rowoff * 4;
#pragma unroll
            for (int j = 0; j < CPL; j++) {
                g_cand_val[ob + j] = sv[q4][j];
                g_cand_idx[ob + j] = si_[q4][j];
            }
        }
#undef LDG_T
#undef STS_T
}

// ---------------- K3: two-phase rank-select -> exact rescore -> top-16 ---------
__global__ __launch_bounds__(256) void final_kernel(const float* __restrict__ mem,
                                                    float* __restrict__ out,
                                                    int n_mem, int P) {
    __shared__ unsigned long long keys[PMAX_PAD];
    __shared__ int   si[PMAX_PAD];
    __shared__ unsigned long long maxv[256];
    __shared__ unsigned long long Tsh;
    __shared__ int   scount;
    __shared__ int   sslot[512];
    __shared__ int   ci[CAND];
    __shared__ float ev[CAND];
    __shared__ unsigned long long k2[CAND];
    __shared__ float wv[TOPK]; __shared__ int wi[TOPK];

    const int q = blockIdx.x, tid = threadIdx.x, lane = tid & 31, w = tid >> 5;

    for (int j = tid; j < PMAX_PAD; j += 256) {
        if (j < P) {
            keys[j] = sort_key(g_cand_val[(size_t)q * P + j], g_cand_idx[(size_t)q * P + j]);
            si[j] = g_cand_idx[(size_t)q * P + j];
        } else { keys[j] = 0ull; si[j] = 0x7FFFFFFF; }
    }
    if (tid == 0) scount = 0;
    if (tid < CAND) ci[tid] = 0x7FFFFFFF;
    __syncthreads();

    // phase 1: per-thread max of owned 19 keys -> 32nd-largest thread-max = T
    unsigned long long mk[19];
#pragma unroll
    for (int i = 0; i < 19; i++) mk[i] = keys[tid + i * 256];
    unsigned long long mymax = mk[0];
#pragma unroll
    for (int i = 1; i < 19; i++) mymax = (mk[i] > mymax) ? mk[i] : mymax;
    maxv[tid] = mymax;
    __syncthreads();
    {
        int r = 0;
        for (int j = 0; j < 256; j += 8) {
            int add = 0;
#pragma unroll
            for (int u = 0; u < 8; u++) add += (maxv[j + u] > mymax) ? 1 : 0;
            r += add;
        }
        if (r == CAND - 1) Tsh = mymax;   // keys are distinct (index in low bits)
    }
    __syncthreads();
    const unsigned long long T = Tsh;

    // survivors: keys >= T (superset of exact top-CAND; bounded by 512 slots)
#pragma unroll
    for (int i = 0; i < 19; i++) {
        if (mk[i] >= T && mk[i] != 0ull) {
            const int pos = atomicAdd(&scount, 1);
            if (pos < 512) sslot[pos] = tid + i * 256;
        }
    }
    __syncthreads();

    // phase 2: rank only survivors against the full pool
    const int S = min(scount, 512);
    for (int s = tid; s < S; s += 256) {
        const unsigned long long mine = keys[sslot[s]];
        int r = 0;
        for (int j = 0; j < PMAX_PAD; j += 8) {
            int add = 0;
#pragma unroll
            for (int u = 0; u < 8; u++) add += (keys[j + u] > mine) ? 1 : 0;
            r += add;
        }
        if (r < CAND) ci[r] = si[sslot[s]];
    }
    __syncthreads();

    // exact fp32 rescore of 32 candidates
    const float* qv = g_q + q * OUT_DIM;
    for (int c = w; c < CAND; c += 8) {
        const int id = ci[c];
        float sum = 0.f;
        if (id < n_mem) {
            const float* row = mem + (size_t)id * OUT_DIM;
#pragma unroll
            for (int d = lane; d < OUT_DIM; d += 32) sum += row[d] * qv[d];
        }
#pragma unroll
        for (int o = 16; o; o >>= 1) sum += __shfl_xor_sync(0xffffffffu, sum, o);
        if (lane == 0) ev[c] = (id < n_mem) ? sum : -FLT_MAX;
    }
    __syncthreads();

    if (tid < CAND) k2[tid] = sort_key(ev[tid], ci[tid]);
    __syncthreads();
    if (tid < CAND) {
        const unsigned long long mine = k2[tid];
        int r = 0;
#pragma unroll
        for (int j = 0; j < CAND; j++)
            if (k2[j] > mine) r++;
        if (r < TOPK) { wv[r] = ev[tid]; wi[r] = ci[tid]; }
    }
    __syncthreads();

    float* out_scores = out;
    float* out_idx    = out + NQ * TOPK;
    float* out_feats  = out + 2 * NQ * TOPK;

    if (tid < TOPK) {
        out_scores[q * TOPK + tid] = wv[tid];
        out_idx[q * TOPK + tid]    = (float)wi[tid];
    }
#pragma unroll 1
    for (int kk = 0; kk < TOPK; kk++)
        out_feats[(size_t)(q * TOPK + kk) * OUT_DIM + tid] = mem[(size_t)wi[kk] * OUT_DIM + tid];
}

// ---------------- launch ------------------------------------------------------
extern "C" void kernel_launch(void* const* d_in, const int* in_sizes, int n_in,
                              void* d_out, int out_size) {
    const float* hidden = (const float*)d_in[0];
    const float* Wp     = (const float*)d_in[1];
    const float* bp     = (const float*)d_in[2];
    const float* mem    = (const float*)d_in[3];
    int n_mem = in_sizes[3] / OUT_DIM;
    if (n_mem > N_MEM_MAX) n_mem = N_MEM_MAX;
    const int ntiles = (n_mem + TROWS - 1) / TROWS;

    int dev = 0;
    cudaGetDevice(&dev);
    int nsm = 148;
    cudaDeviceGetAttribute(&nsm, cudaDevAttrMultiProcessorCount, dev);
    if (nsm < 1) nsm = 148;
    if (nsm > NBLK_MAX) nsm = NBLK_MAX;
    if (nsm > ntiles) nsm = ntiles;

    cudaFuncSetAttribute(score_kernel, cudaFuncAttributeMaxDynamicSharedMemorySize, K2_SMEM);

    proj_kernel<<<128, 256>>>(hidden, Wp, bp);
    ln_kernel<<<NQ, 256>>>();
    score_kernel<<<nsm, K2_THREADS, K2_SMEM>>>(mem, n_mem, ntiles);
    final_kernel<<<NQ, 256>>>(mem, (float*)d_out, n_mem, nsm * 32);
}

// round 13
// speedup vs baseline: 1.6775x; 1.6775x over previous
#include <cuda_runtime.h>
#include <cuda_fp16.h>
#include <cfloat>
#include <cstdint>

#define NUM_HEADS 4
#define OUT_DIM   256
#define HID       512
#define NQ        256
#define TOPK      16
#define N_MEM_MAX 500000
#define CAND      32
#define CPB       4                       // candidates per (query, half, block)
#define NBLK_MAX  152
#define POOL_MAX  (2 * NBLK_MAX * CPB)    // 1216 per query
#define PMAX_PAD  1280                    // 5 * 256

// ---------------- static scratch ---------------------------------------------
__device__ __align__(16) float    g_qpre[64 * NUM_HEADS * OUT_DIM];
__device__ __align__(16) float    g_q [NQ * OUT_DIM];
__device__ __align__(16) __half   g_qh[NQ * OUT_DIM];
__device__ float g_cand_val[NQ * POOL_MAX];
__device__ int   g_cand_idx[NQ * POOL_MAX];

// ---------------- helpers ------------------------------------------------------
__device__ __forceinline__ uint32_t smem_u32(const void* p) {
    return (uint32_t)__cvta_generic_to_shared(p);
}
// pack two fp32 -> f16x2 (F2FP class, rt=2 — cheap)
__device__ __forceinline__ uint32_t f16x2_pack(float lo, float hi) {
    uint32_t r;
    asm("cvt.rn.f16x2.f32 %0, %1, %2;" : "=r"(r) : "f"(hi), "f"(lo));
    return r;
}
__device__ __forceinline__ void ldsm_x4(uint32_t& r0, uint32_t& r1, uint32_t& r2, uint32_t& r3,
                                        uint32_t addr) {
    asm volatile("ldmatrix.sync.aligned.m8n8.x4.shared.b16 {%0,%1,%2,%3}, [%4];"
                 : "=r"(r0), "=r"(r1), "=r"(r2), "=r"(r3) : "r"(addr));
}
// fp16 in, fp16 accum: D{d0,d1} (each 2xf16), historically 2x rate of f32-accum
__device__ __forceinline__ void mma_f16acc(uint32_t* d,
                                           uint32_t a0, uint32_t a1, uint32_t a2, uint32_t a3,
                                           uint32_t b0, uint32_t b1) {
    asm volatile("mma.sync.aligned.m16n8k16.row.col.f16.f16.f16.f16 "
                 "{%0,%1}, {%2,%3,%4,%5}, {%6,%7}, {%0,%1};"
                 : "+r"(d[0]), "+r"(d[1])
                 : "r"(a0), "r"(a1), "r"(a2), "r"(a3), "r"(b0), "r"(b1));
}
__device__ __forceinline__ unsigned long long sort_key(float v, int idx) {
    uint32_t fb = __float_as_uint(v);
    fb ^= (fb & 0x80000000u) ? 0xFFFFFFFFu : 0x80000000u;
    return ((unsigned long long)fb << 32) | (uint32_t)(~idx);
}

// ---------------- K1a: proj = hidden @ Wp + bp (128 blocks) -------------------
__global__ __launch_bounds__(256) void proj_kernel(const float* __restrict__ hidden,
                                                   const float* __restrict__ Wp,
                                                   const float* __restrict__ bp) {
    const int tid = threadIdx.x;
    const int jb = blockIdx.x & 31, bh = blockIdx.x >> 5;
    const int j  = jb * 32 + (tid & 31);
    const int b0 = bh * 16 + (tid >> 5) * 2;
    float acc0 = 0.f, acc1 = 0.f;
#pragma unroll 4
    for (int k = 0; k < HID; k++) {
        const float wv = __ldg(&Wp[k * (NUM_HEADS * OUT_DIM) + j]);
        acc0 = fmaf(__ldg(&hidden[(b0 + 0) * HID + k]), wv, acc0);
        acc1 = fmaf(__ldg(&hidden[(b0 + 1) * HID + k]), wv, acc1);
    }
    const float bias = __ldg(&bp[j]);
    g_qpre[(b0 + 0) * (NUM_HEADS * OUT_DIM) + j] = acc0 + bias;
    g_qpre[(b0 + 1) * (NUM_HEADS * OUT_DIM) + j] = acc1 + bias;
}

// ---------------- K1b: layernorm ----------------------------------------------
__global__ __launch_bounds__(256) void ln_kernel() {
    __shared__ float red[OUT_DIM];
    const int qidx = blockIdx.x;
    const int h = qidx >> 6, b = qidx & 63, d = threadIdx.x;

    const float x = g_qpre[b * (NUM_HEADS * OUT_DIM) + h * OUT_DIM + d];
    red[d] = x; __syncthreads();
    for (int s = 128; s > 0; s >>= 1) { if (d < s) red[d] += red[d + s]; __syncthreads(); }
    const float mean = red[0] * (1.0f / OUT_DIM);
    __syncthreads();
    const float dx = x - mean;
    red[d] = dx * dx; __syncthreads();
    for (int s = 128; s > 0; s >>= 1) { if (d < s) red[d] += red[d + s]; __syncthreads(); }
    const float var = red[0] * (1.0f / OUT_DIM);

    const float o = dx * rsqrtf(var + 1e-5f);
    g_q [qidx * OUT_DIM + d] = o;
    g_qh[qidx * OUT_DIM + d] = __float2half(o);
}

// ---------------- K2: fp16 mma (f16 accum), 3-deep A ring, 1 barrier/tile -----
#define K2_THREADS 512
#define TROWS 32
#define LDB   264                        // f16 elems per row (528B), ldsm conflict-free
#define LDBB  (LDB * 2)                  // 528
#define B_BYTES (NQ * LDBB)              // 135168
#define A_BYTES (TROWS * LDBB)           // 16896
#define A_OFF   B_BYTES
#define SBP   260
#define SB_BYTES (TROWS * SBP * 2)       // 16640
#define SB_OFF  (A_OFF + 3 * A_BYTES)    // 185856
#define K2_SMEM (SB_OFF + 2 * SB_BYTES)  // 219136

#define INS4(v, r)                                                        \
    do {                                                                  \
        t4v[tminpos] = (v); t4i[tminpos] = (r);                           \
        tmin = t4v[0]; tminpos = 0;                                       \
        _Pragma("unroll")                                                 \
        for (int jj = 1; jj < CPB; jj++)                                  \
            if (t4v[jj] < tmin) { tmin = t4v[jj]; tminpos = jj; }         \
    } while (0)

__global__ __launch_bounds__(K2_THREADS, 1) void score_kernel(const float* __restrict__ mem,
                                                              int n_mem, int ntiles) {
    extern __shared__ char sm[];
    char* Bs = sm;                        // queries f16 [256][LDB]
    const uint32_t sb = smem_u32(sm);

    const int tid = threadIdx.x, lane = tid & 31, w = tid >> 5;   // 16 warps

    // B fill: 256 queries x 512B f16
    {
        const uint2* src = (const uint2*)g_qh;
        for (int p = tid; p < NQ * 64; p += K2_THREADS) {
            const int q = p >> 6, c4 = p & 63;
            *(uint2*)(Bs + q * LDBB + c4 * 8) = src[p];
        }
    }

    // selection state: thread covers query (tid&255), half (tid>>8) -> 16 rows
    const int myq = tid & 255, half = tid >> 8;
    float t4v[CPB]; int t4i[CPB];
#pragma unroll
    for (int j = 0; j < CPB; j++) { t4v[j] = -FLT_MAX; t4i[j] = 0x7FFFFFFF; }
    float tmin = -FLT_MAX; int tminpos = 0;

    // A loader: thread -> row tid>>4 (0..31), float col (tid&15)*16
    const int ar = tid >> 4, ac = (tid & 15) * 16;
    const uint32_t asts0 = sb + A_OFF + ar * LDBB + ac * 2;

    float4 f[4];
#define LDG_T(tl)                                                                   \
    do {                                                                            \
        const int rg_ = (tl) * TROWS + ar;                                          \
        if (rg_ < n_mem) {                                                          \
            const float4* s = (const float4*)(mem + (size_t)rg_ * OUT_DIM + ac);    \
            f[0] = s[0]; f[1] = s[1]; f[2] = s[2]; f[3] = s[3];                     \
        } else {                                                                    \
            f[0] = f[1] = f[2] = f[3] = make_float4(0.f, 0.f, 0.f, 0.f);            \
        }                                                                           \
    } while (0)

#define STS_T(bufi)                                                                 \
    do {                                                                            \
        const uint32_t d = asts0 + (bufi) * A_BYTES;                                \
        uint4 o0, o1;                                                               \
        o0.x = f16x2_pack(f[0].x, f[0].y); o0.y = f16x2_pack(f[0].z, f[0].w);       \
        o0.z = f16x2_pack(f[1].x, f[1].y); o0.w = f16x2_pack(f[1].z, f[1].w);       \
        o1.x = f16x2_pack(f[2].x, f[2].y); o1.y = f16x2_pack(f[2].z, f[2].w);       \
        o1.z = f16x2_pack(f[3].x, f[3].y); o1.w = f16x2_pack(f[3].z, f[3].w);       \
        asm volatile("st.shared.v4.b32 [%0], {%1,%2,%3,%4};" ::                     \
            "r"(d), "r"(o0.x), "r"(o0.y), "r"(o0.z), "r"(o0.w) : "memory");         \
        asm volatile("st.shared.v4.b32 [%0], {%1,%2,%3,%4};" ::                     \
            "r"(d + 16), "r"(o1.x), "r"(o1.y), "r"(o1.z), "r"(o1.w) : "memory");    \
    } while (0)

    // prologue: stage tile t0 into buf0, prefetch t1 into regs
    LDG_T(blockIdx.x);
    STS_T(0);
    {
        const int t1 = blockIdx.x + gridDim.x;
        if (t1 < ntiles) LDG_T(t1);
    }
    __syncthreads();

    // warp tile: 32 rows x 16 queries (q block = w*16)
    const uint32_t bB = sb + (w * 16 + (lane & 15)) * LDBB + (lane >> 4) * 16;

    int it = 0, cur = 0, nxt = 1;
    for (int t = blockIdx.x; t < ntiles; t += gridDim.x, it++) {
        const int tn  = t + gridDim.x;
        const int tn2 = t + 2 * gridDim.x;

        if (tn < ntiles) STS_T(nxt);      // stage t+1 (buf free since mma(t-2))
        if (tn2 < ntiles) LDG_T(tn2);     // prefetch t+2 into regs

        const uint32_t aB = sb + A_OFF + cur * A_BYTES
                          + (lane & 15) * LDBB + (lane >> 4) * 16;

        // f16 accumulators: [mt][nt][2 regs], each reg = 2 halves (cols q, q+1)
        uint32_t acc[2][2][2];
#pragma unroll
        for (int mt = 0; mt < 2; mt++)
#pragma unroll
            for (int nt = 0; nt < 2; nt++) { acc[mt][nt][0] = 0u; acc[mt][nt][1] = 0u; }

#pragma unroll
        for (int kt = 0; kt < 16; kt++) {
            uint32_t a0, a1, a2, a3, a4, a5, a6, a7;
            ldsm_x4(a0, a1, a2, a3, aB + kt * 32);
            ldsm_x4(a4, a5, a6, a7, aB + 16 * LDBB + kt * 32);
            uint32_t b0, b1, b2, b3;
            ldsm_x4(b0, b1, b2, b3, bB + kt * 32);
            mma_f16acc(acc[0][0], a0, a1, a2, a3, b0, b2);
            mma_f16acc(acc[0][1], a0, a1, a2, a3, b1, b3);
            mma_f16acc(acc[1][0], a4, a5, a6, a7, b0, b2);
            mma_f16acc(acc[1][1], a4, a5, a6, a7, b1, b3);
        }

        // epilogue: accumulators are already packed f16x2 along q -> direct u32 STS
        __half* Sb = (__half*)(sm + SB_OFF + (it & 1) * SB_BYTES);
#pragma unroll
        for (int mt = 0; mt < 2; mt++) {
            const int rl = mt * 16 + (lane >> 2);
#pragma unroll
            for (int nt = 0; nt < 2; nt++) {
                const int q = w * 16 + nt * 8 + (lane & 3) * 2;
                *(uint32_t*)(Sb + rl * SBP + q)       = acc[mt][nt][0];
                *(uint32_t*)(Sb + (rl + 8) * SBP + q) = acc[mt][nt][1];
            }
        }

        __syncthreads();   // ONE barrier: Sb[it&1] + A[nxt] visible; A[cur] reads done

        // fused selection(t): reads Sb[it&1]
        {
            const int rb = t * TROWS + half * 16;
            const int rmax = min(16, n_mem - rb);
            const __half* Sp = Sb + half * 16 * SBP + myq;
#pragma unroll 4
            for (int r = 0; r < 16; r++) {
                const float v = __half2float(Sp[r * SBP]);
                if (v > tmin && r < rmax) INS4(v, rb + r);
            }
        }

        cur = nxt; nxt = (nxt == 2) ? 0 : nxt + 1;
    }

    const int ob = ((myq * 2 + half) * gridDim.x + blockIdx.x) * CPB;
#pragma unroll
    for (int j = 0; j < CPB; j++) { g_cand_val[ob + j] = t4v[j]; g_cand_idx[ob + j] = t4i[j]; }
#undef LDG_T
#undef STS_T
}

// ---------------- K3: two-phase rank-select -> exact rescore -> top-16 ---------
__global__ __launch_bounds__(256) void final_kernel(const float* __restrict__ mem,
                                                    float* __restrict__ out,
                                                    int n_mem, int P) {
    __shared__ unsigned long long keys[PMAX_PAD];
    __shared__ int   si[PMAX_PAD];
    __shared__ unsigned long long maxv[256];
    __shared__ unsigned long long Tsh;
    __shared__ int   scount;
    __shared__ int   sslot[PMAX_PAD];
    __shared__ int   ci[CAND];
    __shared__ float ev[CAND];
    __shared__ unsigned long long k2[CAND];
    __shared__ float wv[TOPK]; __shared__ int wi[TOPK];

    const int q = blockIdx.x, tid = threadIdx.x, lane = tid & 31, w = tid >> 5;

    for (int j = tid; j < PMAX_PAD; j += 256) {
        if (j < P) {
            keys[j] = sort_key(g_cand_val[q * P + j], g_cand_idx[q * P + j]);
            si[j] = g_cand_idx[q * P + j];
        } else { keys[j] = 0ull; si[j] = 0x7FFFFFFF; }
    }
    if (tid == 0) scount = 0;
    if (tid < CAND) ci[tid] = 0x7FFFFFFF;
    __syncthreads();

    // phase 1: per-thread max of owned 5 keys -> 32nd-largest thread-max = T
    unsigned long long mk[5];
#pragma unroll
    for (int i = 0; i < 5; i++) mk[i] = keys[tid + i * 256];
    unsigned long long mymax = mk[0];
#pragma unroll
    for (int i = 1; i < 5; i++) mymax = (mk[i] > mymax) ? mk[i] : mymax;
    maxv[tid] = mymax;
    __syncthreads();
    {
        int r = 0;
        for (int j = 0; j < 256; j += 8) {
            int add = 0;
#pragma unroll
            for (int u = 0; u < 8; u++) add += (maxv[j + u] > mymax) ? 1 : 0;
            r += add;
        }
        if (r == CAND - 1) Tsh = mymax;   // keys are distinct (index in low bits)
    }
    __syncthreads();
    const unsigned long long T = Tsh;

    // survivors: keys >= T (superset of exact top-CAND)
#pragma unroll
    for (int i = 0; i < 5; i++) {
        if (mk[i] >= T && mk[i] != 0ull) {
            const int pos = atomicAdd(&scount, 1);
            sslot[pos] = tid + i * 256;
        }
    }
    __syncthreads();

    // phase 2: rank only survivors against the full pool
    const int S = scount;
    for (int s = tid; s < S; s += 256) {
        const unsigned long long mine = keys[sslot[s]];
        int r = 0;
        for (int j = 0; j < PMAX_PAD; j += 8) {
            int add = 0;
#pragma unroll
            for (int u = 0; u < 8; u++) add += (keys[j + u] > mine) ? 1 : 0;
            r += add;
        }
        if (r < CAND) ci[r] = si[sslot[s]];
    }
    __syncthreads();

    // exact fp32 rescore of 32 candidates
    const float* qv = g_q + q * OUT_DIM;
    for (int c = w; c < CAND; c += 8) {
        const int id = ci[c];
        float sum = 0.f;
        if (id < n_mem) {
            const float* row = mem + (size_t)id * OUT_DIM;
#pragma unroll
            for (int d = lane; d < OUT_DIM; d += 32) sum += row[d] * qv[d];
        }
#pragma unroll
        for (int o = 16; o; o >>= 1) sum += __shfl_xor_sync(0xffffffffu, sum, o);
        if (lane == 0) ev[c] = (id < n_mem) ? sum : -FLT_MAX;
    }
    __syncthreads();

    if (tid < CAND) k2[tid] = sort_key(ev[tid], ci[tid]);
    __syncthreads();
    if (tid < CAND) {
        const unsigned long long mine = k2[tid];
        int r = 0;
#pragma unroll
        for (int j = 0; j < CAND; j++)
            if (k2[j] > mine) r++;
        if (r < TOPK) { wv[r] = ev[tid]; wi[r] = ci[tid]; }
    }
    __syncthreads();

    float* out_scores = out;
    float* out_idx    = out + NQ * TOPK;
    float* out_feats  = out + 2 * NQ * TOPK;

    if (tid < TOPK) {
        out_scores[q * TOPK + tid] = wv[tid];
        out_idx[q * TOPK + tid]    = (float)wi[tid];
    }
#pragma unroll 1
    for (int kk = 0; kk < TOPK; kk++)
        out_feats[(size_t)(q * TOPK + kk) * OUT_DIM + tid] = mem[(size_t)wi[kk] * OUT_DIM + tid];
}

// ---------------- launch ------------------------------------------------------
extern "C" void kernel_launch(void* const* d_in, const int* in_sizes, int n_in,
                              void* d_out, int out_size) {
    const float* hidden = (const float*)d_in[0];
    const float* Wp     = (const float*)d_in[1];
    const float* bp     = (const float*)d_in[2];
    const float* mem    = (const float*)d_in[3];
    int n_mem = in_sizes[3] / OUT_DIM;
    if (n_mem > N_MEM_MAX) n_mem = N_MEM_MAX;
    const int ntiles = (n_mem + TROWS - 1) / TROWS;

    int dev = 0;
    cudaGetDevice(&dev);
    int nsm = 148;
    cudaDeviceGetAttribute(&nsm, cudaDevAttrMultiProcessorCount, dev);
    if (nsm < 1) nsm = 148;
    if (nsm > NBLK_MAX) nsm = NBLK_MAX;
    if (nsm > ntiles) nsm = ntiles;

    cudaFuncSetAttribute(score_kernel, cudaFuncAttributeMaxDynamicSharedMemorySize, K2_SMEM);

    proj_kernel<<<128, 256>>>(hidden, Wp, bp);
    ln_kernel<<<NQ, 256>>>();
    score_kernel<<<nsm, K2_THREADS, K2_SMEM>>>(mem, n_mem, ntiles);
    final_kernel<<<NQ, 256>>>(mem, (float*)d_out, n_mem, 2 * nsm * CPB);
}